// round 1
// baseline (speedup 1.0000x reference)
#include <cuda_runtime.h>
#include <math.h>

#define F        128
#define KAGG     16
#define ROWS     32          // output rows per CTA
#define THREADS  256
#define B        256

// Scratch (static __device__ arrays: allowed; no runtime allocation)
__device__ float g_h2[B * 256 * F];   // 33.5 MB
__device__ float g_h1[B * 16  * F];   // 2 MB
__device__ float g_h0[B * F];         // 128 KB

// ---------------------------------------------------------------------------
// Fused SAGE layer: out[r] = relu( concat(mean_k nbr[r*K+k], self[r]) @ W + b )
//   nbr : [Rtotal*KAGG, F]   self : [Rtotal, F]
//   W   : [2F, F] row-major  bias : [F]      out : [Rtotal, F]
// One CTA = 32 rows. SMEM: W (128 KB) + concat activations (32 KB).
// ---------------------------------------------------------------------------
__global__ void __launch_bounds__(THREADS, 1)
sage_layer_kernel(const float* __restrict__ nbr,
                  const float* __restrict__ selfx,
                  const float* __restrict__ W,
                  const float* __restrict__ bias,
                  float* __restrict__ out)
{
    extern __shared__ float sm[];
    float* Ws = sm;                 // [2F][F] = 32768 floats
    float* As = sm + 2 * F * F;     // [ROWS][2F] = 8192 floats

    const int tid = threadIdx.x;
    const int wid = tid >> 5;
    const int lid = tid & 31;

    // ---- stage W into SMEM (float4, coalesced) ----
    {
        float4*       Ws4 = (float4*)Ws;
        const float4* Wg4 = (const float4*)W;
        #pragma unroll
        for (int t = 0; t < (2 * F * F / 4) / THREADS; ++t)
            Ws4[tid + t * THREADS] = Wg4[tid + t * THREADS];
    }

    // ---- aggregate neighbors + stage concat activations ----
    const int rg0 = blockIdx.x * ROWS;
    #pragma unroll
    for (int rr = 0; rr < ROWS / 8; ++rr) {     // 4 rows per warp
        const int r  = wid * (ROWS / 8) + rr;
        const int rg = rg0 + r;
        const float4* nb = (const float4*)(nbr + (size_t)rg * KAGG * F);
        float4 acc = make_float4(0.f, 0.f, 0.f, 0.f);
        #pragma unroll
        for (int k = 0; k < KAGG; ++k) {
            float4 v = nb[k * (F / 4) + lid];
            acc.x += v.x; acc.y += v.y; acc.z += v.z; acc.w += v.w;
        }
        const float s = 1.0f / (float)KAGG;
        float4* ar = (float4*)(As + r * 2 * F);
        ar[lid] = make_float4(acc.x * s, acc.y * s, acc.z * s, acc.w * s);
        ar[(F / 4) + lid] = ((const float4*)(selfx + (size_t)rg * F))[lid];
    }
    __syncthreads();

    // ---- register-tiled GEMM: warp -> 4 rows, lane -> cols 4*lid..4*lid+3 ----
    const float* a0 = As + (wid * 4 + 0) * 2 * F;
    const float* a1 = As + (wid * 4 + 1) * 2 * F;
    const float* a2 = As + (wid * 4 + 2) * 2 * F;
    const float* a3 = As + (wid * 4 + 3) * 2 * F;
    const float4* Ws4 = (const float4*)Ws;

    float4 c0 = make_float4(0.f, 0.f, 0.f, 0.f);
    float4 c1 = c0, c2 = c0, c3 = c0;

    #pragma unroll 8
    for (int f = 0; f < 2 * F; ++f) {
        float4 wv = Ws4[f * (F / 4) + lid];   // LDS.128, conflict-free
        float v0 = a0[f], v1 = a1[f], v2 = a2[f], v3 = a3[f];  // LDS broadcast
        c0.x += wv.x * v0; c0.y += wv.y * v0; c0.z += wv.z * v0; c0.w += wv.w * v0;
        c1.x += wv.x * v1; c1.y += wv.y * v1; c1.z += wv.z * v1; c1.w += wv.w * v1;
        c2.x += wv.x * v2; c2.y += wv.y * v2; c2.z += wv.z * v2; c2.w += wv.w * v2;
        c3.x += wv.x * v3; c3.y += wv.y * v3; c3.z += wv.z * v3; c3.w += wv.w * v3;
    }

    // ---- bias + relu + store ----
    const float4 bv = ((const float4*)bias)[lid];
    float4* o4 = (float4*)out;
    const int base = (rg0 + wid * 4) * (F / 4) + lid;
    float4 r0 = make_float4(fmaxf(c0.x + bv.x, 0.f), fmaxf(c0.y + bv.y, 0.f),
                            fmaxf(c0.z + bv.z, 0.f), fmaxf(c0.w + bv.w, 0.f));
    float4 r1 = make_float4(fmaxf(c1.x + bv.x, 0.f), fmaxf(c1.y + bv.y, 0.f),
                            fmaxf(c1.z + bv.z, 0.f), fmaxf(c1.w + bv.w, 0.f));
    float4 r2 = make_float4(fmaxf(c2.x + bv.x, 0.f), fmaxf(c2.y + bv.y, 0.f),
                            fmaxf(c2.z + bv.z, 0.f), fmaxf(c2.w + bv.w, 0.f));
    float4 r3 = make_float4(fmaxf(c3.x + bv.x, 0.f), fmaxf(c3.y + bv.y, 0.f),
                            fmaxf(c3.z + bv.z, 0.f), fmaxf(c3.w + bv.w, 0.f));
    o4[base + 0 * (F / 4)] = r0;
    o4[base + 1 * (F / 4)] = r1;
    o4[base + 2 * (F / 4)] = r2;
    o4[base + 3 * (F / 4)] = r3;
}

// ---------------------------------------------------------------------------
// Head: z = h0 @ lin1_W + lin1_b ; BatchNorm (batch stats, biased var) ;
//       out = sigmoid(zn @ lin2_W + lin2_b).  Single CTA, 256 threads
//       (one per batch row); deterministic tree reductions for stats.
// ---------------------------------------------------------------------------
__global__ void __launch_bounds__(256, 1)
head_kernel(const float* __restrict__ h0,
            const float* __restrict__ l1W,   // [F, 8]
            const float* __restrict__ l1b,   // [8]
            const float* __restrict__ gamma, // [8]
            const float* __restrict__ beta,  // [8]
            const float* __restrict__ l2W,   // [8, 2]
            const float* __restrict__ l2b,   // [2]
            float* __restrict__ out)         // [B, 2]
{
    __shared__ float ssum[256 * 8];
    __shared__ float ssq [256 * 8];

    const int i = threadIdx.x;

    float z[8];
    #pragma unroll
    for (int j = 0; j < 8; ++j) z[j] = l1b[j];

    const float* hr = h0 + (size_t)i * F;
    #pragma unroll 4
    for (int f = 0; f < F; ++f) {
        float h = hr[f];
        #pragma unroll
        for (int j = 0; j < 8; ++j) z[j] += h * l1W[f * 8 + j];
    }

    #pragma unroll
    for (int j = 0; j < 8; ++j) {
        ssum[i * 8 + j] = z[j];
        ssq [i * 8 + j] = z[j] * z[j];
    }
    __syncthreads();

    for (int s = 128; s > 0; s >>= 1) {
        if (i < s) {
            #pragma unroll
            for (int j = 0; j < 8; ++j) {
                ssum[i * 8 + j] += ssum[(i + s) * 8 + j];
                ssq [i * 8 + j] += ssq [(i + s) * 8 + j];
            }
        }
        __syncthreads();
    }

    float zn[8];
    #pragma unroll
    for (int j = 0; j < 8; ++j) {
        float mu  = ssum[j] * (1.0f / 256.0f);
        float var = ssq[j] * (1.0f / 256.0f) - mu * mu;
        float rs  = rsqrtf(var + 1e-5f);
        zn[j] = (z[j] - mu) * rs * gamma[j] + beta[j];
    }

    #pragma unroll
    for (int c = 0; c < 2; ++c) {
        float o = l2b[c];
        #pragma unroll
        for (int j = 0; j < 8; ++j) o += zn[j] * l2W[j * 2 + c];
        out[i * 2 + c] = 1.0f / (1.0f + expf(-o));
    }
}

// ---------------------------------------------------------------------------
extern "C" void kernel_launch(void* const* d_in, const int* in_sizes, int n_in,
                              void* d_out, int out_size)
{
    const float* x0    = (const float*)d_in[0];
    const float* x1    = (const float*)d_in[1];
    const float* x2    = (const float*)d_in[2];
    const float* x3    = (const float*)d_in[3];
    const float* W0    = (const float*)d_in[4];
    const float* b0    = (const float*)d_in[5];
    const float* W1    = (const float*)d_in[6];
    const float* b1    = (const float*)d_in[7];
    const float* W2    = (const float*)d_in[8];
    const float* b2    = (const float*)d_in[9];
    const float* l1W   = (const float*)d_in[10];
    const float* l1b   = (const float*)d_in[11];
    const float* gamma = (const float*)d_in[12];
    const float* beta  = (const float*)d_in[13];
    const float* l2W   = (const float*)d_in[14];
    const float* l2b   = (const float*)d_in[15];
    float* out = (float*)d_out;

    void *p2 = nullptr, *p1 = nullptr, *p0 = nullptr;
    cudaGetSymbolAddress(&p2, g_h2);
    cudaGetSymbolAddress(&p1, g_h1);
    cudaGetSymbolAddress(&p0, g_h0);
    float* h2 = (float*)p2;
    float* h1 = (float*)p1;
    float* h0 = (float*)p0;

    const int smem = (2 * F * F + ROWS * 2 * F) * (int)sizeof(float); // 163840 B
    cudaFuncSetAttribute(sage_layer_kernel,
                         cudaFuncAttributeMaxDynamicSharedMemorySize, smem);

    // Layer i=3: [B*256] rows  (neighbors: x3, self: x2)
    sage_layer_kernel<<<(B * 256) / ROWS, THREADS, smem>>>(x3, x2, W2, b2, h2);
    // Layer i=2: [B*16] rows   (neighbors: h2, self: x1)
    sage_layer_kernel<<<(B * 16) / ROWS, THREADS, smem>>>(h2, x1, W1, b1, h1);
    // Layer i=1: [B] rows      (neighbors: h1, self: x0)
    sage_layer_kernel<<<B / ROWS, THREADS, smem>>>(h1, x0, W0, b0, h0);
    // Classifier head
    head_kernel<<<1, 256>>>(h0, l1W, l1b, gamma, beta, l2W, l2b, out);
}

// round 3
// speedup vs baseline: 1.2630x; 1.2630x over previous
#include <cuda_runtime.h>
#include <math.h>

#define F        128
#define TWO_F    256
#define KAGG     16
#define TILE     32          // rows per tile
#define NPROD    4           // producer warps
#define THREADS  256
#define B        256

// Scratch (static __device__ arrays: allowed; no runtime allocation)
__device__ float g_h2[65536 * F];   // 33.5 MB
__device__ float g_h1[4096  * F];   // 2 MB
__device__ float g_h0[256   * F];   // 128 KB

// ---- packed f32x2 helpers ------------------------------------------------
__device__ __forceinline__ unsigned long long pack2(float x) {
    unsigned long long r;
    asm("mov.b64 %0, {%1, %1};" : "=l"(r) : "f"(x));
    return r;
}
__device__ __forceinline__ void fma2(unsigned long long& d,
                                     unsigned long long a,
                                     unsigned long long b) {
    asm("fma.rn.f32x2 %0, %1, %2, %0;" : "+l"(d) : "l"(a), "l"(b));
}
__device__ __forceinline__ void unpack2(unsigned long long v, float& lo, float& hi) {
    asm("mov.b64 {%0, %1}, %2;" : "=f"(lo), "=f"(hi) : "l"(v));
}

// ---------------------------------------------------------------------------
// Warp-specialized fused SAGE layer.
//   out[r] = relu( concat(mean_k nbr[r*16+k], self[r]) @ W + b )
// Persistent CTAs (grid ~148). Per CTA: W staged in SMEM (128 KB),
// double-buffered 32-row activation tiles (2 x 32 KB).
// Warps 0-3: producers (aggregate + stage concat rows).
// Warps 4-7: consumers (register-tiled GEMM, packed FFMA2, full FMA rate).
// ---------------------------------------------------------------------------
__global__ void __launch_bounds__(THREADS, 1)
sage_layer(const float* __restrict__ nbr,
           const float* __restrict__ selfx,
           const float* __restrict__ W,
           const float* __restrict__ bias,
           float* __restrict__ out,
           int ntiles)
{
    extern __shared__ float sm[];
    float* Ws    = sm;                       // [2F][F] = 32768 floats (128 KB)
    float* Abuf0 = sm + TWO_F * F;           // [TILE][2F] = 8192 floats (32 KB)
    float* Abuf1 = Abuf0 + TILE * TWO_F;     // second buffer (32 KB)

    const int tid = threadIdx.x;
    const int wid = tid >> 5;
    const int lid = tid & 31;

    // ---- stage W into SMEM (coalesced float4) ----
    {
        float4*       d = (float4*)Ws;
        const float4* s = (const float4*)W;
        #pragma unroll
        for (int t = 0; t < (TWO_F * F / 4) / THREADS; ++t)
            d[tid + t * THREADS] = s[tid + t * THREADS];
    }
    __syncthreads();

    // tiles handled by this CTA: blockIdx.x, +gridDim.x, ...
    int n = 0;
    for (int t = blockIdx.x; t < ntiles; t += gridDim.x) n++;
    if (n == 0) return;

    const bool producer = (wid < NPROD);
    const float4 bv = ((const float4*)bias)[lid];   // cols 4*lid..4*lid+3

    for (int i = 0; i <= n; ++i) {
        float* bufP = (i & 1) ? Abuf1 : Abuf0;
        float* bufC = (i & 1) ? Abuf0 : Abuf1;

        if (producer) {
            if (i < n) {
                const int tile = blockIdx.x + i * gridDim.x;
                #pragma unroll
                for (int rr = 0; rr < 8; ++rr) {           // 8 rows per producer warp
                    const int  r  = wid * 8 + rr;
                    const long rg = (long)tile * TILE + r;
                    const float4* nb = (const float4*)(nbr + rg * (KAGG * F)) + lid;
                    float4 acc = make_float4(0.f, 0.f, 0.f, 0.f);
                    #pragma unroll
                    for (int k = 0; k < KAGG; ++k) {
                        float4 v = nb[k * (F / 4)];
                        acc.x += v.x; acc.y += v.y; acc.z += v.z; acc.w += v.w;
                    }
                    float4 sv = ((const float4*)(selfx + rg * F))[lid];
                    float4* ar = (float4*)(bufP + r * TWO_F);
                    const float s = 1.0f / 16.0f;
                    ar[lid]          = make_float4(acc.x * s, acc.y * s,
                                                   acc.z * s, acc.w * s);
                    ar[F / 4 + lid]  = sv;
                }
            }
        } else {
            if (i >= 1) {
                const int tile = blockIdx.x + (i - 1) * gridDim.x;
                const int cw   = wid - NPROD;              // 0..3
                const float* arow = bufC + (cw * 8) * TWO_F;
                const ulonglong2* Wp = (const ulonglong2*)Ws;  // 32 per row, idx f*32+lid

                unsigned long long acc[8][2];
                #pragma unroll
                for (int r = 0; r < 8; ++r) { acc[r][0] = 0ull; acc[r][1] = 0ull; }

                #pragma unroll 2
                for (int f4 = 0; f4 < TWO_F / 4; ++f4) {
                    float4 a[8];
                    #pragma unroll
                    for (int r = 0; r < 8; ++r)            // LDS.128 broadcast
                        a[r] = ((const float4*)(arow + r * TWO_F))[f4];
                    #pragma unroll
                    for (int j = 0; j < 4; ++j) {
                        const int f = f4 * 4 + j;
                        ulonglong2 wv = Wp[f * (F / 4) + lid];  // 16B/lane, conflict-free
                        #pragma unroll
                        for (int r = 0; r < 8; ++r) {
                            float av = (j == 0) ? a[r].x : (j == 1) ? a[r].y
                                     : (j == 2) ? a[r].z : a[r].w;
                            unsigned long long ap = pack2(av);
                            fma2(acc[r][0], wv.x, ap);
                            fma2(acc[r][1], wv.y, ap);
                        }
                    }
                }

                // bias + relu + coalesced store
                #pragma unroll
                for (int r = 0; r < 8; ++r) {
                    float c0, c1, c2, c3;
                    unpack2(acc[r][0], c0, c1);
                    unpack2(acc[r][1], c2, c3);
                    float4 o = make_float4(fmaxf(c0 + bv.x, 0.f),
                                           fmaxf(c1 + bv.y, 0.f),
                                           fmaxf(c2 + bv.z, 0.f),
                                           fmaxf(c3 + bv.w, 0.f));
                    const long rg = (long)tile * TILE + cw * 8 + r;
                    ((float4*)(out + rg * F))[lid] = o;
                }
            }
        }
        __syncthreads();
    }
}

// ---------------------------------------------------------------------------
// Head: z = h0 @ lin1_W + lin1_b ; BatchNorm (batch stats) ; sigmoid(lin2).
// l1W staged in SMEM, h0 via float4. Deterministic tree reductions.
// ---------------------------------------------------------------------------
__global__ void __launch_bounds__(256, 1)
head_kernel(const float* __restrict__ h0,
            const float* __restrict__ l1W,   // [F, 8]
            const float* __restrict__ l1b,   // [8]
            const float* __restrict__ gamma, // [8]
            const float* __restrict__ beta,  // [8]
            const float* __restrict__ l2W,   // [8, 2]
            const float* __restrict__ l2b,   // [2]
            float* __restrict__ out)         // [B, 2]
{
    __shared__ float sW[F * 8];
    __shared__ float ssum[256 * 8];
    __shared__ float ssq [256 * 8];

    const int i = threadIdx.x;

    for (int t = i; t < F * 8; t += 256) sW[t] = l1W[t];
    __syncthreads();

    float z[8];
    #pragma unroll
    for (int j = 0; j < 8; ++j) z[j] = l1b[j];

    const float4* hr = (const float4*)(h0 + (size_t)i * F);
    #pragma unroll
    for (int f4 = 0; f4 < F / 4; ++f4) {
        float4 h = hr[f4];
        #pragma unroll
        for (int j = 0; j < 8; ++j)
            z[j] += h.x * sW[(4 * f4 + 0) * 8 + j]
                  + h.y * sW[(4 * f4 + 1) * 8 + j]
                  + h.z * sW[(4 * f4 + 2) * 8 + j]
                  + h.w * sW[(4 * f4 + 3) * 8 + j];
    }

    #pragma unroll
    for (int j = 0; j < 8; ++j) {
        ssum[i * 8 + j] = z[j];
        ssq [i * 8 + j] = z[j] * z[j];
    }
    __syncthreads();

    for (int s = 128; s > 0; s >>= 1) {
        if (i < s) {
            #pragma unroll
            for (int j = 0; j < 8; ++j) {
                ssum[i * 8 + j] += ssum[(i + s) * 8 + j];
                ssq [i * 8 + j] += ssq [(i + s) * 8 + j];
            }
        }
        __syncthreads();
    }

    float zn[8];
    #pragma unroll
    for (int j = 0; j < 8; ++j) {
        float mu  = ssum[j] * (1.0f / 256.0f);
        float var = ssq[j] * (1.0f / 256.0f) - mu * mu;
        float rs  = rsqrtf(var + 1e-5f);
        zn[j] = (z[j] - mu) * rs * gamma[j] + beta[j];
    }

    #pragma unroll
    for (int c = 0; c < 2; ++c) {
        float o = l2b[c];
        #pragma unroll
        for (int j = 0; j < 8; ++j) o += zn[j] * l2W[j * 2 + c];
        out[i * 2 + c] = 1.0f / (1.0f + expf(-o));
    }
}

// ---------------------------------------------------------------------------
extern "C" void kernel_launch(void* const* d_in, const int* in_sizes, int n_in,
                              void* d_out, int out_size)
{
    const float* x0    = (const float*)d_in[0];
    const float* x1    = (const float*)d_in[1];
    const float* x2    = (const float*)d_in[2];
    const float* x3    = (const float*)d_in[3];
    const float* W0    = (const float*)d_in[4];
    const float* b0    = (const float*)d_in[5];
    const float* W1    = (const float*)d_in[6];
    const float* b1    = (const float*)d_in[7];
    const float* W2    = (const float*)d_in[8];
    const float* b2    = (const float*)d_in[9];
    const float* l1W   = (const float*)d_in[10];
    const float* l1b   = (const float*)d_in[11];
    const float* gamma = (const float*)d_in[12];
    const float* beta  = (const float*)d_in[13];
    const float* l2W   = (const float*)d_in[14];
    const float* l2b   = (const float*)d_in[15];
    float* out = (float*)d_out;

    void *p2 = nullptr, *p1 = nullptr, *p0 = nullptr;
    cudaGetSymbolAddress(&p2, g_h2);
    cudaGetSymbolAddress(&p1, g_h1);
    cudaGetSymbolAddress(&p0, g_h0);
    float* h2 = (float*)p2;
    float* h1 = (float*)p1;
    float* h0 = (float*)p0;

    const int smem = (TWO_F * F + 2 * TILE * TWO_F) * (int)sizeof(float); // 192 KB
    cudaFuncSetAttribute(sage_layer,
                         cudaFuncAttributeMaxDynamicSharedMemorySize, smem);

    const int grid = 148;
    // Layer i=3: 65536 rows (neighbors: x3, self: x2) -> h2
    sage_layer<<<grid, THREADS, smem>>>(x3, x2, W2, b2, h2, 65536 / TILE);
    // Layer i=2: 4096 rows (neighbors: h2, self: x1) -> h1
    sage_layer<<<grid, THREADS, smem>>>(h2, x1, W1, b1, h1, 4096 / TILE);
    // Layer i=1: 256 rows (neighbors: h1, self: x0) -> h0
    sage_layer<<<grid, THREADS, smem>>>(h1, x0, W0, b0, h0, 256 / TILE);
    // Classifier head
    head_kernel<<<1, 256>>>(h0, l1W, l1b, gamma, beta, l2W, l2b, out);
}

// round 4
// speedup vs baseline: 1.2888x; 1.0204x over previous
#include <cuda_runtime.h>
#include <math.h>

#define F        128
#define TWO_F    256
#define KAGG     16
#define TILE     32          // rows per tile
#define NPROD    4           // producer warps
#define THREADS  256
#define B        256

// Scratch (static __device__ arrays: allowed; no runtime allocation)
__device__ float g_h2[65536 * F];   // 33.5 MB
__device__ float g_h1[4096  * F];   // 2 MB
__device__ float g_h0[256   * F];   // 128 KB

// ---- packed f32x2 helpers ------------------------------------------------
__device__ __forceinline__ unsigned long long pack2(float x) {
    unsigned long long r;
    asm("mov.b64 %0, {%1, %1};" : "=l"(r) : "f"(x));
    return r;
}
__device__ __forceinline__ void fma2(unsigned long long& d,
                                     unsigned long long a,
                                     unsigned long long b) {
    asm("fma.rn.f32x2 %0, %1, %2, %0;" : "+l"(d) : "l"(a), "l"(b));
}
__device__ __forceinline__ void unpack2(unsigned long long v, float& lo, float& hi) {
    asm("mov.b64 {%0, %1}, %2;" : "=f"(lo), "=f"(hi) : "l"(v));
}
__device__ __forceinline__ void cpa16(void* dst_smem, const void* src) {
    unsigned d = (unsigned)__cvta_generic_to_shared(dst_smem);
    asm volatile("cp.async.ca.shared.global [%0], [%1], 16;" :: "r"(d), "l"(src));
}

// ---------------------------------------------------------------------------
// Warp-specialized fused SAGE layer.
//   out[r] = relu( concat(mean_k nbr[r*16+k], self[r]) @ W + b )
// Persistent CTAs (grid 148). W staged in SMEM (128 KB),
// double-buffered 32-row activation tiles (2 x 32 KB).
// Warps 0-3: producers. k-outer round-robin over 8 rows for deep MLP;
//            self rows via cp.async (no regs, latency-immune).
// Warps 4-7: consumers (register-tiled GEMM, packed FFMA2).
// ---------------------------------------------------------------------------
__global__ void __launch_bounds__(THREADS, 1)
sage_layer(const float* __restrict__ nbr,
           const float* __restrict__ selfx,
           const float* __restrict__ W,
           const float* __restrict__ bias,
           float* __restrict__ out,
           int ntiles)
{
    extern __shared__ float sm[];
    float* Ws    = sm;                       // [2F][F] = 32768 floats (128 KB)
    float* Abuf0 = sm + TWO_F * F;           // [TILE][2F] = 8192 floats (32 KB)
    float* Abuf1 = Abuf0 + TILE * TWO_F;     // second buffer (32 KB)

    const int tid = threadIdx.x;
    const int wid = tid >> 5;
    const int lid = tid & 31;

    // ---- stage W into SMEM (coalesced float4) ----
    {
        float4*       d = (float4*)Ws;
        const float4* s = (const float4*)W;
        #pragma unroll
        for (int t = 0; t < (TWO_F * F / 4) / THREADS; ++t)
            d[tid + t * THREADS] = s[tid + t * THREADS];
    }
    __syncthreads();

    int n = 0;
    for (int t = blockIdx.x; t < ntiles; t += gridDim.x) n++;
    if (n == 0) return;

    const bool producer = (wid < NPROD);
    const float4 bv = ((const float4*)bias)[lid];   // cols 4*lid..4*lid+3

    for (int i = 0; i <= n; ++i) {
        float* bufP = (i & 1) ? Abuf1 : Abuf0;
        float* bufC = (i & 1) ? Abuf0 : Abuf1;

        if (producer) {
            if (i < n) {
                const int  tile = blockIdx.x + i * gridDim.x;
                const long r0g  = (long)tile * TILE + wid * 8;   // first of 8 rows

                // self rows -> SMEM via cp.async (latency-immune, zero regs)
                #pragma unroll
                for (int r = 0; r < 8; ++r)
                    cpa16(bufP + (wid * 8 + r) * TWO_F + F + lid * 4,
                          selfx + (r0g + r) * F + lid * 4);
                asm volatile("cp.async.commit_group;");

                // neighbor aggregation: k-outer, 8 rows round-robin.
                // 8 independent LDG.128 per k-step -> deep MLP.
                const float4* base = (const float4*)(nbr + r0g * (KAGG * F)) + lid;
                float4 acc[8];
                #pragma unroll
                for (int r = 0; r < 8; ++r) acc[r] = make_float4(0.f, 0.f, 0.f, 0.f);

                #pragma unroll
                for (int k = 0; k < KAGG; ++k) {
                    float4 v[8];
                    #pragma unroll
                    for (int r = 0; r < 8; ++r)
                        v[r] = base[(long)r * (KAGG * F / 4) + k * (F / 4)];
                    #pragma unroll
                    for (int r = 0; r < 8; ++r) {
                        acc[r].x += v[r].x; acc[r].y += v[r].y;
                        acc[r].z += v[r].z; acc[r].w += v[r].w;
                    }
                }

                const float s = 1.0f / 16.0f;
                #pragma unroll
                for (int r = 0; r < 8; ++r)
                    ((float4*)(bufP + (wid * 8 + r) * TWO_F))[lid] =
                        make_float4(acc[r].x * s, acc[r].y * s,
                                    acc[r].z * s, acc[r].w * s);

                asm volatile("cp.async.wait_group 0;");
            }
        } else {
            if (i >= 1) {
                const int tile = blockIdx.x + (i - 1) * gridDim.x;
                const int cw   = wid - NPROD;              // 0..3
                const float* arow = bufC + (cw * 8) * TWO_F;
                const ulonglong2* Wp = (const ulonglong2*)Ws;

                unsigned long long acc[8][2];
                #pragma unroll
                for (int r = 0; r < 8; ++r) { acc[r][0] = 0ull; acc[r][1] = 0ull; }

                #pragma unroll 2
                for (int f4 = 0; f4 < TWO_F / 4; ++f4) {
                    float4 a[8];
                    #pragma unroll
                    for (int r = 0; r < 8; ++r)            // LDS broadcast (16B)
                        a[r] = ((const float4*)(arow + r * TWO_F))[f4];
                    #pragma unroll
                    for (int j = 0; j < 4; ++j) {
                        const int f = f4 * 4 + j;
                        ulonglong2 wv = Wp[f * (F / 4) + lid];  // LDS.128, conflict-free
                        #pragma unroll
                        for (int r = 0; r < 8; ++r) {
                            float av = (j == 0) ? a[r].x : (j == 1) ? a[r].y
                                     : (j == 2) ? a[r].z : a[r].w;
                            unsigned long long ap = pack2(av);
                            fma2(acc[r][0], wv.x, ap);
                            fma2(acc[r][1], wv.y, ap);
                        }
                    }
                }

                // bias + relu + coalesced store
                #pragma unroll
                for (int r = 0; r < 8; ++r) {
                    float c0, c1, c2, c3;
                    unpack2(acc[r][0], c0, c1);
                    unpack2(acc[r][1], c2, c3);
                    float4 o = make_float4(fmaxf(c0 + bv.x, 0.f),
                                           fmaxf(c1 + bv.y, 0.f),
                                           fmaxf(c2 + bv.z, 0.f),
                                           fmaxf(c3 + bv.w, 0.f));
                    const long rg = (long)tile * TILE + cw * 8 + r;
                    ((float4*)(out + rg * F))[lid] = o;
                }
            }
        }
        __syncthreads();
    }
}

// ---------------------------------------------------------------------------
// Head: z = h0 @ lin1_W + lin1_b ; BatchNorm (batch stats) ; sigmoid(lin2).
// Warp-shuffle reductions (deterministic), 2 barriers total.
// ---------------------------------------------------------------------------
__global__ void __launch_bounds__(256, 1)
head_kernel(const float* __restrict__ h0,
            const float* __restrict__ l1W,   // [F, 8]
            const float* __restrict__ l1b,   // [8]
            const float* __restrict__ gamma, // [8]
            const float* __restrict__ beta,  // [8]
            const float* __restrict__ l2W,   // [8, 2]
            const float* __restrict__ l2b,   // [2]
            float* __restrict__ out)         // [B, 2]
{
    __shared__ float sW[F * 8];
    __shared__ float wsum[8][8];
    __shared__ float wsq [8][8];

    const int i   = threadIdx.x;
    const int wid = i >> 5;
    const int lid = i & 31;

    for (int t = i; t < F * 8; t += 256) sW[t] = l1W[t];
    __syncthreads();

    float z[8];
    #pragma unroll
    for (int j = 0; j < 8; ++j) z[j] = l1b[j];

    const float4* hr = (const float4*)(h0 + (size_t)i * F);
    #pragma unroll
    for (int f4 = 0; f4 < F / 4; ++f4) {
        float4 h = hr[f4];
        #pragma unroll
        for (int j = 0; j < 8; ++j)
            z[j] += h.x * sW[(4 * f4 + 0) * 8 + j]
                  + h.y * sW[(4 * f4 + 1) * 8 + j]
                  + h.z * sW[(4 * f4 + 2) * 8 + j]
                  + h.w * sW[(4 * f4 + 3) * 8 + j];
    }

    // warp-level reduction (deterministic butterfly)
    float rs_[8], rq_[8];
    #pragma unroll
    for (int j = 0; j < 8; ++j) { rs_[j] = z[j]; rq_[j] = z[j] * z[j]; }
    #pragma unroll
    for (int off = 16; off > 0; off >>= 1) {
        #pragma unroll
        for (int j = 0; j < 8; ++j) {
            rs_[j] += __shfl_xor_sync(0xffffffffu, rs_[j], off);
            rq_[j] += __shfl_xor_sync(0xffffffffu, rq_[j], off);
        }
    }
    if (lid == 0) {
        #pragma unroll
        for (int j = 0; j < 8; ++j) { wsum[wid][j] = rs_[j]; wsq[wid][j] = rq_[j]; }
    }
    __syncthreads();

    float zn[8];
    #pragma unroll
    for (int j = 0; j < 8; ++j) {
        float su = 0.f, sq = 0.f;
        #pragma unroll
        for (int w = 0; w < 8; ++w) { su += wsum[w][j]; sq += wsq[w][j]; }
        float mu  = su * (1.0f / 256.0f);
        float var = sq * (1.0f / 256.0f) - mu * mu;
        float rs  = rsqrtf(var + 1e-5f);
        zn[j] = (z[j] - mu) * rs * gamma[j] + beta[j];
    }

    #pragma unroll
    for (int c = 0; c < 2; ++c) {
        float o = l2b[c];
        #pragma unroll
        for (int j = 0; j < 8; ++j) o += zn[j] * l2W[j * 2 + c];
        out[i * 2 + c] = 1.0f / (1.0f + expf(-o));
    }
}

// ---------------------------------------------------------------------------
extern "C" void kernel_launch(void* const* d_in, const int* in_sizes, int n_in,
                              void* d_out, int out_size)
{
    const float* x0    = (const float*)d_in[0];
    const float* x1    = (const float*)d_in[1];
    const float* x2    = (const float*)d_in[2];
    const float* x3    = (const float*)d_in[3];
    const float* W0    = (const float*)d_in[4];
    const float* b0    = (const float*)d_in[5];
    const float* W1    = (const float*)d_in[6];
    const float* b1    = (const float*)d_in[7];
    const float* W2    = (const float*)d_in[8];
    const float* b2    = (const float*)d_in[9];
    const float* l1W   = (const float*)d_in[10];
    const float* l1b   = (const float*)d_in[11];
    const float* gamma = (const float*)d_in[12];
    const float* beta  = (const float*)d_in[13];
    const float* l2W   = (const float*)d_in[14];
    const float* l2b   = (const float*)d_in[15];
    float* out = (float*)d_out;

    void *p2 = nullptr, *p1 = nullptr, *p0 = nullptr;
    cudaGetSymbolAddress(&p2, g_h2);
    cudaGetSymbolAddress(&p1, g_h1);
    cudaGetSymbolAddress(&p0, g_h0);
    float* h2 = (float*)p2;
    float* h1 = (float*)p1;
    float* h0 = (float*)p0;

    const int smem = (TWO_F * F + 2 * TILE * TWO_F) * (int)sizeof(float); // 192 KB
    cudaFuncSetAttribute(sage_layer,
                         cudaFuncAttributeMaxDynamicSharedMemorySize, smem);

    const int grid = 148;
    // Layer i=3: 65536 rows (neighbors: x3, self: x2) -> h2
    sage_layer<<<grid, THREADS, smem>>>(x3, x2, W2, b2, h2, 65536 / TILE);
    // Layer i=2: 4096 rows (neighbors: h2, self: x1) -> h1
    sage_layer<<<grid, THREADS, smem>>>(h2, x1, W1, b1, h1, 4096 / TILE);
    // Layer i=1: 256 rows (neighbors: h1, self: x0) -> h0
    sage_layer<<<grid, THREADS, smem>>>(h1, x0, W0, b0, h0, 256 / TILE);
    // Classifier head
    head_kernel<<<1, 256>>>(h0, l1W, l1b, gamma, beta, l2W, l2b, out);
}

// round 5
// speedup vs baseline: 1.3476x; 1.0456x over previous
#include <cuda_runtime.h>
#include <math.h>

#define F        128
#define TWO_F    256
#define KAGG     16
#define TILE     32          // rows per tile
#define NPROD    12          // producer warps
#define THREADS  512
#define B        256

// Scratch (static __device__ arrays: allowed; no runtime allocation)
__device__ float g_h2[65536 * F];   // 33.5 MB
__device__ float g_h1[4096  * F];   // 2 MB
__device__ float g_h0[256   * F];   // 128 KB

// ---- packed f32x2 helpers ------------------------------------------------
__device__ __forceinline__ unsigned long long pack2(float x) {
    unsigned long long r;
    asm("mov.b64 %0, {%1, %1};" : "=l"(r) : "f"(x));
    return r;
}
__device__ __forceinline__ void fma2(unsigned long long& d,
                                     unsigned long long a,
                                     unsigned long long b) {
    asm("fma.rn.f32x2 %0, %1, %2, %0;" : "+l"(d) : "l"(a), "l"(b));
}
__device__ __forceinline__ void unpack2(unsigned long long v, float& lo, float& hi) {
    asm("mov.b64 {%0, %1}, %2;" : "=f"(lo), "=f"(hi) : "l"(v));
}
__device__ __forceinline__ void cpa16(void* dst_smem, const void* src) {
    unsigned d = (unsigned)__cvta_generic_to_shared(dst_smem);
    asm volatile("cp.async.ca.shared.global [%0], [%1], 16;" :: "r"(d), "l"(src));
}

// ---------------------------------------------------------------------------
// Warp-specialized fused SAGE layer.
//   out[r] = relu( concat(mean_k nbr[r*16+k], self[r]) @ W + b )
// Persistent CTAs (grid 148), 512 threads = 16 warps.
// Warps 0-11 : producers. Each handles rows r = wid, wid+12, wid+24 of the
//              32-row tile. 12 warps x ~14 in-flight LDG.128 => DRAM-BW-bound
//              aggregation instead of per-warp latency-bound.
// Warps 12-15: consumers, one per SMSP, 8 rows each (keeps W smem re-read
//              at 4 x 131 KB/tile = 4096 cyc < 8192-cyc FFMA2 pipe floor).
// W staged in SMEM (128 KB) + double-buffered 32-row tiles (2 x 32 KB).
// ---------------------------------------------------------------------------
__global__ void __launch_bounds__(THREADS, 1)
sage_layer(const float* __restrict__ nbr,
           const float* __restrict__ selfx,
           const float* __restrict__ W,
           const float* __restrict__ bias,
           float* __restrict__ out,
           int ntiles)
{
    extern __shared__ float sm[];
    float* Ws    = sm;                       // [2F][F] = 32768 floats (128 KB)
    float* Abuf0 = sm + TWO_F * F;           // [TILE][2F] (32 KB)
    float* Abuf1 = Abuf0 + TILE * TWO_F;     // second buffer (32 KB)

    const int tid = threadIdx.x;
    const int wid = tid >> 5;
    const int lid = tid & 31;

    // ---- stage W into SMEM (coalesced float4) ----
    {
        float4*       d = (float4*)Ws;
        const float4* s = (const float4*)W;
        #pragma unroll
        for (int t = 0; t < (TWO_F * F / 4) / THREADS; ++t)
            d[tid + t * THREADS] = s[tid + t * THREADS];
    }
    __syncthreads();

    int n = 0;
    for (int t = blockIdx.x; t < ntiles; t += gridDim.x) n++;
    if (n == 0) return;

    const bool producer = (wid < NPROD);
    const float4 bv = ((const float4*)bias)[lid];   // cols 4*lid..4*lid+3

    for (int i = 0; i <= n; ++i) {
        float* bufP = (i & 1) ? Abuf1 : Abuf0;
        float* bufC = (i & 1) ? Abuf0 : Abuf1;

        if (producer) {
            if (i < n) {
                const int  tile = blockIdx.x + i * gridDim.x;
                const long tg0  = (long)tile * TILE;

                // self rows -> SMEM via cp.async (latency-immune, zero regs)
                for (int r = wid; r < TILE; r += NPROD)
                    cpa16(bufP + r * TWO_F + F + lid * 4,
                          selfx + (tg0 + r) * F + lid * 4);
                asm volatile("cp.async.commit_group;");

                // neighbor aggregation: each producer warp owns 2-3 rows;
                // full 16-load batch per row, 12 warps give chip-level MLP.
                for (int r = wid; r < TILE; r += NPROD) {
                    const float4* nb =
                        (const float4*)(nbr + (tg0 + r) * (KAGG * F)) + lid;
                    float4 v[KAGG];
                    #pragma unroll
                    for (int k = 0; k < KAGG; ++k)
                        v[k] = nb[k * (F / 4)];
                    // pairwise tree reduce (short dependency chains)
                    #pragma unroll
                    for (int s2 = KAGG / 2; s2 > 0; s2 >>= 1)
                        #pragma unroll
                        for (int k = 0; k < s2; ++k) {
                            v[k].x += v[k + s2].x; v[k].y += v[k + s2].y;
                            v[k].z += v[k + s2].z; v[k].w += v[k + s2].w;
                        }
                    const float s = 1.0f / 16.0f;
                    ((float4*)(bufP + r * TWO_F))[lid] =
                        make_float4(v[0].x * s, v[0].y * s,
                                    v[0].z * s, v[0].w * s);
                }
                asm volatile("cp.async.wait_group 0;");
            }
        } else {
            if (i >= 1) {
                const int tile = blockIdx.x + (i - 1) * gridDim.x;
                const int cw   = wid - NPROD;              // 0..3
                const float* arow = bufC + (cw * 8) * TWO_F;
                const ulonglong2* Wp = (const ulonglong2*)Ws;

                unsigned long long acc[8][2];
                #pragma unroll
                for (int r = 0; r < 8; ++r) { acc[r][0] = 0ull; acc[r][1] = 0ull; }

                #pragma unroll 2
                for (int f4 = 0; f4 < TWO_F / 4; ++f4) {
                    float4 a[8];
                    #pragma unroll
                    for (int r = 0; r < 8; ++r)            // LDS broadcast (16B)
                        a[r] = ((const float4*)(arow + r * TWO_F))[f4];
                    #pragma unroll
                    for (int j = 0; j < 4; ++j) {
                        const int f = f4 * 4 + j;
                        ulonglong2 wv = Wp[f * (F / 4) + lid];  // LDS.128, conflict-free
                        #pragma unroll
                        for (int r = 0; r < 8; ++r) {
                            float av = (j == 0) ? a[r].x : (j == 1) ? a[r].y
                                     : (j == 2) ? a[r].z : a[r].w;
                            unsigned long long ap = pack2(av);
                            fma2(acc[r][0], wv.x, ap);
                            fma2(acc[r][1], wv.y, ap);
                        }
                    }
                }

                // bias + relu + coalesced store
                #pragma unroll
                for (int r = 0; r < 8; ++r) {
                    float c0, c1, c2, c3;
                    unpack2(acc[r][0], c0, c1);
                    unpack2(acc[r][1], c2, c3);
                    float4 o = make_float4(fmaxf(c0 + bv.x, 0.f),
                                           fmaxf(c1 + bv.y, 0.f),
                                           fmaxf(c2 + bv.z, 0.f),
                                           fmaxf(c3 + bv.w, 0.f));
                    const long rg = (long)tile * TILE + cw * 8 + r;
                    ((float4*)(out + rg * F))[lid] = o;
                }
            }
        }
        __syncthreads();
    }
}

// ---------------------------------------------------------------------------
// Head: z = h0 @ lin1_W + lin1_b ; BatchNorm (batch stats) ; sigmoid(lin2).
// Warp-shuffle reductions (deterministic), 2 barriers total.
// ---------------------------------------------------------------------------
__global__ void __launch_bounds__(256, 1)
head_kernel(const float* __restrict__ h0,
            const float* __restrict__ l1W,   // [F, 8]
            const float* __restrict__ l1b,   // [8]
            const float* __restrict__ gamma, // [8]
            const float* __restrict__ beta,  // [8]
            const float* __restrict__ l2W,   // [8, 2]
            const float* __restrict__ l2b,   // [2]
            float* __restrict__ out)         // [B, 2]
{
    __shared__ float sW[F * 8];
    __shared__ float wsum[8][8];
    __shared__ float wsq [8][8];

    const int i   = threadIdx.x;
    const int wid = i >> 5;
    const int lid = i & 31;

    for (int t = i; t < F * 8; t += 256) sW[t] = l1W[t];
    __syncthreads();

    float z[8];
    #pragma unroll
    for (int j = 0; j < 8; ++j) z[j] = l1b[j];

    const float4* hr = (const float4*)(h0 + (size_t)i * F);
    #pragma unroll
    for (int f4 = 0; f4 < F / 4; ++f4) {
        float4 h = hr[f4];
        #pragma unroll
        for (int j = 0; j < 8; ++j)
            z[j] += h.x * sW[(4 * f4 + 0) * 8 + j]
                  + h.y * sW[(4 * f4 + 1) * 8 + j]
                  + h.z * sW[(4 * f4 + 2) * 8 + j]
                  + h.w * sW[(4 * f4 + 3) * 8 + j];
    }

    // warp-level reduction (deterministic butterfly)
    float rs_[8], rq_[8];
    #pragma unroll
    for (int j = 0; j < 8; ++j) { rs_[j] = z[j]; rq_[j] = z[j] * z[j]; }
    #pragma unroll
    for (int off = 16; off > 0; off >>= 1) {
        #pragma unroll
        for (int j = 0; j < 8; ++j) {
            rs_[j] += __shfl_xor_sync(0xffffffffu, rs_[j], off);
            rq_[j] += __shfl_xor_sync(0xffffffffu, rq_[j], off);
        }
    }
    if (lid == 0) {
        #pragma unroll
        for (int j = 0; j < 8; ++j) { wsum[wid][j] = rs_[j]; wsq[wid][j] = rq_[j]; }
    }
    __syncthreads();

    float zn[8];
    #pragma unroll
    for (int j = 0; j < 8; ++j) {
        float su = 0.f, sq = 0.f;
        #pragma unroll
        for (int w = 0; w < 8; ++w) { su += wsum[w][j]; sq += wsq[w][j]; }
        float mu  = su * (1.0f / 256.0f);
        float var = sq * (1.0f / 256.0f) - mu * mu;
        float rs  = rsqrtf(var + 1e-5f);
        zn[j] = (z[j] - mu) * rs * gamma[j] + beta[j];
    }

    #pragma unroll
    for (int c = 0; c < 2; ++c) {
        float o = l2b[c];
        #pragma unroll
        for (int j = 0; j < 8; ++j) o += zn[j] * l2W[j * 2 + c];
        out[i * 2 + c] = 1.0f / (1.0f + expf(-o));
    }
}

// ---------------------------------------------------------------------------
extern "C" void kernel_launch(void* const* d_in, const int* in_sizes, int n_in,
                              void* d_out, int out_size)
{
    const float* x0    = (const float*)d_in[0];
    const float* x1    = (const float*)d_in[1];
    const float* x2    = (const float*)d_in[2];
    const float* x3    = (const float*)d_in[3];
    const float* W0    = (const float*)d_in[4];
    const float* b0    = (const float*)d_in[5];
    const float* W1    = (const float*)d_in[6];
    const float* b1    = (const float*)d_in[7];
    const float* W2    = (const float*)d_in[8];
    const float* b2    = (const float*)d_in[9];
    const float* l1W   = (const float*)d_in[10];
    const float* l1b   = (const float*)d_in[11];
    const float* gamma = (const float*)d_in[12];
    const float* beta  = (const float*)d_in[13];
    const float* l2W   = (const float*)d_in[14];
    const float* l2b   = (const float*)d_in[15];
    float* out = (float*)d_out;

    void *p2 = nullptr, *p1 = nullptr, *p0 = nullptr;
    cudaGetSymbolAddress(&p2, g_h2);
    cudaGetSymbolAddress(&p1, g_h1);
    cudaGetSymbolAddress(&p0, g_h0);
    float* h2 = (float*)p2;
    float* h1 = (float*)p1;
    float* h0 = (float*)p0;

    const int smem = (TWO_F * F + 2 * TILE * TWO_F) * (int)sizeof(float); // 192 KB
    cudaFuncSetAttribute(sage_layer,
                         cudaFuncAttributeMaxDynamicSharedMemorySize, smem);

    const int grid = 148;
    // Layer i=3: 65536 rows (neighbors: x3, self: x2) -> h2
    sage_layer<<<grid, THREADS, smem>>>(x3, x2, W2, b2, h2, 65536 / TILE);
    // Layer i=2: 4096 rows (neighbors: h2, self: x1) -> h1
    sage_layer<<<grid, THREADS, smem>>>(h2, x1, W1, b1, h1, 4096 / TILE);
    // Layer i=1: 256 rows (neighbors: h1, self: x0) -> h0
    sage_layer<<<grid, THREADS, smem>>>(h1, x0, W0, b0, h0, 256 / TILE);
    // Classifier head
    head_kernel<<<1, 256>>>(h0, l1W, l1b, gamma, beta, l2W, l2b, out);
}